// round 4
// baseline (speedup 1.0000x reference)
#include <cuda_runtime.h>
#include <math.h>

#define N_IN   4096
#define N_OUT  1024
#define BATCH  16
#define E_MAX  81920
#define VB_STRIDE (32 * E_MAX)          // per-batch stride in floats

__device__ float g_featT2[N_IN * 512];                       // [n][c*16+b]  8 MB
__device__ float g_Vbuf[(size_t)BATCH * VB_STRIDE];
__device__ int   g_is64;
__device__ int   g_seg[E_MAX];
__device__ int   g_src[E_MAX];

// ---------------- phase -1: dtype detect + index normalize ------------------
__global__ void detect_idx(const int* __restrict__ idx32, int E) {
    __shared__ int any;
    if (threadIdx.x == 0) any = 0;
    __syncthreads();
    int n = min(E, 512);
    int local = 0;
    for (int m = threadIdx.x; m < n; m += 256)
        local |= idx32[4 * m + 1] | idx32[4 * m + 3];
    if (local) atomicOr(&any, 1);
    __syncthreads();
    if (threadIdx.x == 0) g_is64 = any ? 0 : 1;
}

__global__ void convert_idx(const int* __restrict__ idx32, int E) {
    int m = blockIdx.x * 256 + threadIdx.x;
    if (m >= E) return;
    if (g_is64) { g_seg[m] = idx32[4 * m];     g_src[m] = idx32[4 * m + 2]; }
    else        { g_seg[m] = idx32[2 * m];     g_src[m] = idx32[2 * m + 1]; }
}

// ---------------- phase 0: tiled permute feat[b][c][n] -> featT2[n][c*16+b]
__global__ void prep_featT(const float* __restrict__ feat) {
    __shared__ float tile[32][33];
    int n0  = blockIdx.x * 32;
    int cb0 = blockIdx.y * 32;
    int tx = threadIdx.x, ty = threadIdx.y;       // 32 x 8
    #pragma unroll
    for (int i = ty; i < 32; i += 8) {
        int cb = cb0 + i;
        int row = (cb & 15) * 32 + (cb >> 4);     // b*32 + c
        tile[i][tx] = feat[(size_t)row * N_IN + n0 + tx];
    }
    __syncthreads();
    #pragma unroll
    for (int i = ty; i < 32; i += 8)
        g_featT2[(size_t)(n0 + i) * 512 + cb0 + tx] = tile[tx][i];
}

// ---------------- phase A: per-edge filter MLP + apply, writes vals to Vbuf
// 512 threads, 32 edges/block. smem (floats):
//  h1[32][64]     @0      (2048)
//  h2[32][64]     @2048   (2048)
//  g [32][16][36] @4096   (18432)
//  filt[16][32][36] @22528 (18432)
//  locs[64]       @40960
//  goff[1024] int @41024
#define SMEM_A_FLOATS 42048
#define SMEM_A_BYTES  (SMEM_A_FLOATS * 4)

__global__ __launch_bounds__(512, 1) void quad_main(
    const float* __restrict__ W1, const float* __restrict__ W2,
    const float* __restrict__ W3, const float* __restrict__ eval_locs, int E)
{
    extern __shared__ float sm[];
    float* h1_s = sm;
    float* h2_s = sm + 2048;
    float* g_s  = sm + 4096;
    float* f_s  = sm + 22528;
    float* locs = sm + 40960;
    int*   goff = (int*)(sm + 41024);

    const int t   = threadIdx.x;
    const int e0  = blockIdx.x * 32;
    const int net = min(32, E - e0);

    if (t < 2 * net) locs[t] = eval_locs[2 * e0 + t];

    // gather offsets per (e, ci): m = (e0+e)*32+ci ; channel c = m/E, row m%E
    #pragma unroll
    for (int r = 0; r < 2; r++) {
        int p = t + 512 * r;
        int e = p >> 5;
        if (e < net) {
            int m  = (e0 + e) * 32 + (p & 31);
            int c  = m / E;
            int rr = m - c * E;
            goff[p] = g_src[rr] * 512 + c * 16;
        }
    }
    __syncthreads();

    // upfront gather of all 32 edges: g[e][b][ci]  (scattered LDGs in flight early)
    #pragma unroll
    for (int r = 0; r < 32; r++) {
        int i  = t + 512 * r;              // 0..16383
        int p8 = i >> 4;                   // (e,ci) 0..1023
        int b  = i & 15;
        int e  = p8 >> 5, ci = p8 & 31;
        float v = (e < net) ? g_featT2[goff[p8] + b] : 0.f;
        g_s[e * 576 + b * 36 + ci] = v;
    }

    // h1[e][j] = sin(loc_e . W1[:,j])   (0 for padded edges)
    #pragma unroll
    for (int r = 0; r < 4; r++) {
        int id = t + 512 * r;
        int e = id >> 6, j = id & 63;
        float v = 0.f;
        if (e < net)
            v = __sinf(locs[2 * e] * W1[j] + locs[2 * e + 1] * W1[64 + j]);
        h1_s[id] = v;
    }
    __syncthreads();

    // h2: register-blocked — thread owns (e = t>>4, 4 cols j0 = (t&15)*4)
    {
        const int e  = t >> 4;
        const int j0 = (t & 15) * 4;
        float4 acc = make_float4(0.f, 0.f, 0.f, 0.f);
        #pragma unroll
        for (int k = 0; k < 64; k += 4) {
            float4 hv = *(const float4*)&h1_s[e * 64 + k];
            float4 w;
            w = *(const float4*)&W2[(k + 0) * 64 + j0];
            acc.x += hv.x * w.x; acc.y += hv.x * w.y; acc.z += hv.x * w.z; acc.w += hv.x * w.w;
            w = *(const float4*)&W2[(k + 1) * 64 + j0];
            acc.x += hv.y * w.x; acc.y += hv.y * w.y; acc.z += hv.y * w.z; acc.w += hv.y * w.w;
            w = *(const float4*)&W2[(k + 2) * 64 + j0];
            acc.x += hv.z * w.x; acc.y += hv.z * w.y; acc.z += hv.z * w.z; acc.w += hv.z * w.w;
            w = *(const float4*)&W2[(k + 3) * 64 + j0];
            acc.x += hv.w * w.x; acc.y += hv.w * w.y; acc.z += hv.w * w.z; acc.w += hv.w * w.w;
        }
        float4 hv2 = make_float4(__sinf(acc.x), __sinf(acc.y),
                                 __sinf(acc.z), __sinf(acc.w));
        if (e >= net) hv2 = make_float4(0.f, 0.f, 0.f, 0.f);
        *(float4*)&h2_s[e * 64 + j0] = hv2;
    }
    __syncthreads();

    // filter gen: thread owns W3 columns {2t, 2t+1} for all 32 edges.
    // W3 loads software-pipelined one k4-step ahead.
    float2 facc[32];
    #pragma unroll
    for (int e = 0; e < 32; e++) facc[e] = make_float2(0.f, 0.f);

    const float* w3p = W3 + 2 * t;
    float2 w0 = *(const float2*)(w3p + 0 * 1024);
    float2 w1 = *(const float2*)(w3p + 1 * 1024);
    float2 w2 = *(const float2*)(w3p + 2 * 1024);
    float2 w3 = *(const float2*)(w3p + 3 * 1024);

    #pragma unroll
    for (int k4 = 0; k4 < 64; k4 += 4) {
        float2 n0, n1, n2, n3;
        if (k4 < 60) {
            n0 = *(const float2*)(w3p + (k4 + 4) * 1024);
            n1 = *(const float2*)(w3p + (k4 + 5) * 1024);
            n2 = *(const float2*)(w3p + (k4 + 6) * 1024);
            n3 = *(const float2*)(w3p + (k4 + 7) * 1024);
        }
        #pragma unroll
        for (int e = 0; e < 32; e++) {
            float4 h = *(const float4*)&h2_s[e * 64 + k4];
            float ax = facc[e].x, ay = facc[e].y;
            ax += w0.x * h.x; ay += w0.y * h.x;
            ax += w1.x * h.y; ay += w1.y * h.y;
            ax += w2.x * h.z; ay += w2.y * h.z;
            ax += w3.x * h.w; ay += w3.y * h.w;
            facc[e].x = ax; facc[e].y = ay;
        }
        w0 = n0; w1 = n1; w2 = n2; w3 = n3;
    }

    // store/apply mapping
    const int fci = t >> 4;             // col 2t -> ci
    const int fco = (t & 15) * 2;       //        -> co
    const int tt  = t & 127;
    const int ab  = tt >> 3;            // batch
    const int aco = (tt & 7) * 4;       // 4 consecutive co
    const int gid = t >> 7;             // 0..3 -> 4 edges each per sub-phase

    #pragma unroll
    for (int sub = 0; sub < 2; sub++) {
        const int es0 = sub * 16;

        #pragma unroll
        for (int e = 0; e < 16; e++)
            *(float2*)&f_s[e * 1152 + fci * 36 + fco] = facc[es0 + e];
        __syncthreads();

        #pragma unroll
        for (int ee = 0; ee < 4; ee++) {
            int e = gid * 4 + ee;
            if (es0 + e < net) {
                const float* gp = &g_s[(es0 + e) * 576 + ab * 36];
                const float* fp = &f_s[e * 1152 + aco];
                float a0 = 0.f, a1 = 0.f, a2 = 0.f, a3 = 0.f;
                #pragma unroll
                for (int ci4 = 0; ci4 < 32; ci4 += 4) {
                    float4 gv = *(const float4*)&gp[ci4];
                    float4 f0 = *(const float4*)&fp[(ci4 + 0) * 36];
                    float4 f1 = *(const float4*)&fp[(ci4 + 1) * 36];
                    float4 f2 = *(const float4*)&fp[(ci4 + 2) * 36];
                    float4 f3 = *(const float4*)&fp[(ci4 + 3) * 36];
                    a0 += gv.x * f0.x + gv.y * f1.x + gv.z * f2.x + gv.w * f3.x;
                    a1 += gv.x * f0.y + gv.y * f1.y + gv.z * f2.y + gv.w * f3.y;
                    a2 += gv.x * f0.z + gv.y * f1.z + gv.z * f2.z + gv.w * f3.z;
                    a3 += gv.x * f0.w + gv.y * f1.w + gv.z * f2.w + gv.w * f3.w;
                }
                size_t m = (size_t)(e0 + es0 + e) * 32 + aco;
                *(float4*)&g_Vbuf[(size_t)ab * VB_STRIDE + m] =
                    make_float4(a0, a1, a2, a3);
            }
        }
        __syncthreads();
    }
}

// ---------------- phase B: out[b][c][o] = sum over seg-range of Vbuf[b][c*E + r]
__global__ __launch_bounds__(512) void quad_scatter(float* __restrict__ out, int E)
{
    const int o = blockIdx.x;
    int lo = 0, hi = E;
    while (lo < hi) { int m = (lo + hi) >> 1; if (g_seg[m] <  o) lo = m + 1; else hi = m; }
    const int r0 = lo;
    hi = E;
    while (lo < hi) { int m = (lo + hi) >> 1; if (g_seg[m] <= o) lo = m + 1; else hi = m; }
    const int r1 = lo;

    const int b = threadIdx.x >> 5;
    const int l = threadIdx.x & 31;

    for (int c = 0; c < 32; c++) {
        const float* p = &g_Vbuf[(size_t)b * VB_STRIDE + (size_t)c * E];
        float s = 0.f;
        for (int r = r0 + l; r < r1; r += 32) s += p[r];
        #pragma unroll
        for (int d = 16; d; d >>= 1) s += __shfl_xor_sync(0xffffffffu, s, d);
        if (l == 0) out[b * 32768 + c * 1024 + o] = s;
    }
}

extern "C" void kernel_launch(void* const* d_in, const int* in_sizes, int n_in,
                              void* d_out, int out_size) {
    const float* features  = (const float*)d_in[0];
    const float* W1        = (const float*)d_in[1];
    const float* W2        = (const float*)d_in[2];
    const float* W3        = (const float*)d_in[3];
    const float* eval_locs = (const float*)d_in[4];
    const int*   eval_idx  = (const int*)d_in[5];
    float*       out       = (float*)d_out;

    const int E = in_sizes[4] / 2;

    cudaFuncSetAttribute(quad_main, cudaFuncAttributeMaxDynamicSharedMemorySize,
                         SMEM_A_BYTES);

    detect_idx<<<1, 256>>>(eval_idx, E);
    convert_idx<<<(E + 255) / 256, 256>>>(eval_idx, E);
    prep_featT<<<dim3(N_IN / 32, 512 / 32), dim3(32, 8)>>>(features);
    quad_main<<<(E + 31) / 32, 512, SMEM_A_BYTES>>>(W1, W2, W3, eval_locs, E);
    quad_scatter<<<N_OUT, 512>>>(out, E);
}

// round 5
// speedup vs baseline: 1.6674x; 1.6674x over previous
#include <cuda_runtime.h>
#include <math.h>

#define N_IN   4096
#define N_OUT  1024
#define BATCH  16
#define E_MAX  81920
#define VB_STRIDE (32 * E_MAX)

__device__ float g_featT2[N_IN * 512];                 // [n][c*16+b]
__device__ float g_Vbuf[(size_t)BATCH * VB_STRIDE];
__device__ int   g_is64;
__device__ int   g_seg[E_MAX];
__device__ int   g_src[E_MAX];

// ---------------- phase -1: dtype detect + index normalize ------------------
__global__ void detect_idx(const int* __restrict__ idx32, int E) {
    __shared__ int any;
    if (threadIdx.x == 0) any = 0;
    __syncthreads();
    int n = min(E, 512);
    int local = 0;
    for (int m = threadIdx.x; m < n; m += 256)
        local |= idx32[4 * m + 1] | idx32[4 * m + 3];
    if (local) atomicOr(&any, 1);
    __syncthreads();
    if (threadIdx.x == 0) g_is64 = any ? 0 : 1;
}

__global__ void convert_idx(const int* __restrict__ idx32, int E) {
    int m = blockIdx.x * 256 + threadIdx.x;
    if (m >= E) return;
    if (g_is64) { g_seg[m] = idx32[4 * m];     g_src[m] = idx32[4 * m + 2]; }
    else        { g_seg[m] = idx32[2 * m];     g_src[m] = idx32[2 * m + 1]; }
}

// ---------------- phase 0: tiled permute feat[b][c][n] -> featT2[n][c*16+b]
__global__ void prep_featT(const float* __restrict__ feat) {
    __shared__ float tile[32][33];
    int n0  = blockIdx.x * 32;
    int cb0 = blockIdx.y * 32;
    int tx = threadIdx.x, ty = threadIdx.y;       // 32 x 8
    #pragma unroll
    for (int i = ty; i < 32; i += 8) {
        int cb = cb0 + i;
        int row = (cb & 15) * 32 + (cb >> 4);     // b*32 + c
        tile[i][tx] = feat[(size_t)row * N_IN + n0 + tx];
    }
    __syncthreads();
    #pragma unroll
    for (int i = ty; i < 32; i += 8)
        g_featT2[(size_t)(n0 + i) * 512 + cb0 + tx] = tile[tx][i];
}

// ---------------- phase A -----------------------------------------------
// 512 threads, 32 edges/block. smem (floats):
//  h1[32][64]      @0      (2048)
//  h2[32][64]      @2048   (2048)
//  W2s[64][64]     @4096   (4096)
//  g [8][16][36]   @8192   (4608)
//  filt[8][32][36] @12800  (9216)
//  locs[64]        @22016
//  goff[1024] int  @22080
#define SMEM_A_FLOATS 23104
#define SMEM_A_BYTES  (SMEM_A_FLOATS * 4)

__global__ __launch_bounds__(512, 1) void quad_main(
    const float* __restrict__ W1, const float* __restrict__ W2,
    const float* __restrict__ W3, const float* __restrict__ eval_locs, int E)
{
    extern __shared__ float sm[];
    float* h1_s = sm;
    float* h2_s = sm + 2048;
    float* W2s  = sm + 4096;
    float* g_s  = sm + 8192;
    float* f_s  = sm + 12800;
    float* locs = sm + 22016;
    int*   goff = (int*)(sm + 22080);

    const int t   = threadIdx.x;
    const int e0  = blockIdx.x * 32;
    const int net = min(32, E - e0);

    if (t < 2 * net) locs[t] = eval_locs[2 * e0 + t];

    // stage W2 into smem (coalesced, once per block)
    #pragma unroll
    for (int r = 0; r < 8; r++)
        W2s[t + 512 * r] = W2[t + 512 * r];

    // gather offsets per (e, ci): m = (e0+e)*32+ci ; channel c = m/E, row m%E
    #pragma unroll
    for (int r = 0; r < 2; r++) {
        int p = t + 512 * r;
        int e = p >> 5;
        if (e < net) {
            int m  = (e0 + e) * 32 + (p & 31);
            int c  = m / E;
            int rr = m - c * E;
            goff[p] = g_src[rr] * 512 + c * 16;
        }
    }
    __syncthreads();

    // h1[e][j] = sin(loc_e . W1[:,j])   (0 for padded edges)
    #pragma unroll
    for (int r = 0; r < 4; r++) {
        int id = t + 512 * r;
        int e = id >> 6, j = id & 63;
        float v = 0.f;
        if (e < net)
            v = __sinf(locs[2 * e] * W1[j] + locs[2 * e + 1] * W1[64 + j]);
        h1_s[id] = v;
    }
    __syncthreads();

    // h2: register-blocked, W2 from smem. thread owns (e = t>>4, j0 = (t&15)*4)
    {
        const int e  = t >> 4;
        const int j0 = (t & 15) * 4;
        float4 acc = make_float4(0.f, 0.f, 0.f, 0.f);
        #pragma unroll
        for (int k = 0; k < 64; k += 4) {
            float4 hv = *(const float4*)&h1_s[e * 64 + k];
            float4 w;
            w = *(const float4*)&W2s[(k + 0) * 64 + j0];
            acc.x += hv.x * w.x; acc.y += hv.x * w.y; acc.z += hv.x * w.z; acc.w += hv.x * w.w;
            w = *(const float4*)&W2s[(k + 1) * 64 + j0];
            acc.x += hv.y * w.x; acc.y += hv.y * w.y; acc.z += hv.y * w.z; acc.w += hv.y * w.w;
            w = *(const float4*)&W2s[(k + 2) * 64 + j0];
            acc.x += hv.z * w.x; acc.y += hv.z * w.y; acc.z += hv.z * w.z; acc.w += hv.z * w.w;
            w = *(const float4*)&W2s[(k + 3) * 64 + j0];
            acc.x += hv.w * w.x; acc.y += hv.w * w.y; acc.z += hv.w * w.z; acc.w += hv.w * w.w;
        }
        float4 hv2 = make_float4(__sinf(acc.x), __sinf(acc.y),
                                 __sinf(acc.z), __sinf(acc.w));
        if (e >= net) hv2 = make_float4(0.f, 0.f, 0.f, 0.f);
        *(float4*)&h2_s[e * 64 + j0] = hv2;
    }
    __syncthreads();

    // filter gen: thread owns W3 columns {2t, 2t+1} for all 32 edges,
    // W3 loads software-pipelined one k4-step ahead.
    float2 facc[32];
    #pragma unroll
    for (int e = 0; e < 32; e++) facc[e] = make_float2(0.f, 0.f);

    const float* w3p = W3 + 2 * t;
    float2 w0 = *(const float2*)(w3p + 0 * 1024);
    float2 w1 = *(const float2*)(w3p + 1 * 1024);
    float2 w2 = *(const float2*)(w3p + 2 * 1024);
    float2 w3 = *(const float2*)(w3p + 3 * 1024);

    #pragma unroll
    for (int k4 = 0; k4 < 64; k4 += 4) {
        float2 n0, n1, n2, n3;
        if (k4 < 60) {
            n0 = *(const float2*)(w3p + (k4 + 4) * 1024);
            n1 = *(const float2*)(w3p + (k4 + 5) * 1024);
            n2 = *(const float2*)(w3p + (k4 + 6) * 1024);
            n3 = *(const float2*)(w3p + (k4 + 7) * 1024);
        }
        #pragma unroll
        for (int e = 0; e < 32; e++) {
            float4 h = *(const float4*)&h2_s[e * 64 + k4];
            float ax = facc[e].x, ay = facc[e].y;
            ax += w0.x * h.x; ay += w0.y * h.x;
            ax += w1.x * h.y; ay += w1.y * h.y;
            ax += w2.x * h.z; ay += w2.y * h.z;
            ax += w3.x * h.w; ay += w3.y * h.w;
            facc[e].x = ax; facc[e].y = ay;
        }
        w0 = n0; w1 = n1; w2 = n2; w3 = n3;
    }

    // mappings
    const int fci = t >> 4;              // filt store: col 2t -> ci
    const int fco = (t & 15) * 2;
    const int ea  = t >> 6;              // apply: edge within sub (0..7)
    const int b0  = ((t >> 3) & 7) * 2;  //        2 batches
    const int j0  = (t & 7) * 4;         //        4 consecutive co

    #pragma unroll
    for (int sub = 0; sub < 4; sub++) {
        const int es0 = sub * 8;

        // staged gather of 8 edges: g[e][b][ci]
        #pragma unroll
        for (int r = 0; r < 8; r++) {
            int i  = t + 512 * r;             // 0..4095
            int p8 = i >> 4;                  // (e,ci) 0..255
            int b  = i & 15;
            int e  = p8 >> 5, ci = p8 & 31;
            float v = (es0 + e < net) ? g_featT2[goff[(es0 + e) * 32 + ci] + b] : 0.f;
            g_s[e * 576 + b * 36 + ci] = v;
        }
        // store this sub's filters
        #pragma unroll
        for (int e = 0; e < 8; e++)
            *(float2*)&f_s[e * 1152 + fci * 36 + fco] = facc[es0 + e];
        __syncthreads();

        // apply: 2b x 4j register tile per thread, one edge each
        if (es0 + ea < net) {
            const float* gp0 = &g_s[ea * 576 + b0 * 36];
            const float* gp1 = gp0 + 36;
            const float* fp  = &f_s[ea * 1152 + j0];
            float4 a0 = make_float4(0.f, 0.f, 0.f, 0.f);
            float4 a1 = make_float4(0.f, 0.f, 0.f, 0.f);
            #pragma unroll
            for (int ci4 = 0; ci4 < 32; ci4 += 4) {
                float4 gv0 = *(const float4*)&gp0[ci4];
                float4 gv1 = *(const float4*)&gp1[ci4];
                float4 f0 = *(const float4*)&fp[(ci4 + 0) * 36];
                float4 f1 = *(const float4*)&fp[(ci4 + 1) * 36];
                float4 f2 = *(const float4*)&fp[(ci4 + 2) * 36];
                float4 f3 = *(const float4*)&fp[(ci4 + 3) * 36];
                a0.x += gv0.x*f0.x + gv0.y*f1.x + gv0.z*f2.x + gv0.w*f3.x;
                a0.y += gv0.x*f0.y + gv0.y*f1.y + gv0.z*f2.y + gv0.w*f3.y;
                a0.z += gv0.x*f0.z + gv0.y*f1.z + gv0.z*f2.z + gv0.w*f3.z;
                a0.w += gv0.x*f0.w + gv0.y*f1.w + gv0.z*f2.w + gv0.w*f3.w;
                a1.x += gv1.x*f0.x + gv1.y*f1.x + gv1.z*f2.x + gv1.w*f3.x;
                a1.y += gv1.x*f0.y + gv1.y*f1.y + gv1.z*f2.y + gv1.w*f3.y;
                a1.z += gv1.x*f0.z + gv1.y*f1.z + gv1.z*f2.z + gv1.w*f3.z;
                a1.w += gv1.x*f0.w + gv1.y*f1.w + gv1.z*f2.w + gv1.w*f3.w;
            }
            size_t m = (size_t)(e0 + es0 + ea) * 32 + j0;
            *(float4*)&g_Vbuf[(size_t)b0       * VB_STRIDE + m] = a0;
            *(float4*)&g_Vbuf[(size_t)(b0 + 1) * VB_STRIDE + m] = a1;
        }
        __syncthreads();
    }
}

// ---------------- phase B: out[b][c][o] = sum over seg-range of Vbuf[b][c*E + r]
__global__ __launch_bounds__(512) void quad_scatter(float* __restrict__ out, int E)
{
    const int o = blockIdx.x;
    int lo = 0, hi = E;
    while (lo < hi) { int m = (lo + hi) >> 1; if (g_seg[m] <  o) lo = m + 1; else hi = m; }
    const int r0 = lo;
    hi = E;
    while (lo < hi) { int m = (lo + hi) >> 1; if (g_seg[m] <= o) lo = m + 1; else hi = m; }
    const int r1 = lo;

    const int b = threadIdx.x >> 5;
    const int l = threadIdx.x & 31;

    for (int c = 0; c < 32; c++) {
        const float* p = &g_Vbuf[(size_t)b * VB_STRIDE + (size_t)c * E];
        float s = 0.f;
        for (int r = r0 + l; r < r1; r += 32) s += p[r];
        #pragma unroll
        for (int d = 16; d; d >>= 1) s += __shfl_xor_sync(0xffffffffu, s, d);
        if (l == 0) out[b * 32768 + c * 1024 + o] = s;
    }
}

extern "C" void kernel_launch(void* const* d_in, const int* in_sizes, int n_in,
                              void* d_out, int out_size) {
    const float* features  = (const float*)d_in[0];
    const float* W1        = (const float*)d_in[1];
    const float* W2        = (const float*)d_in[2];
    const float* W3        = (const float*)d_in[3];
    const float* eval_locs = (const float*)d_in[4];
    const int*   eval_idx  = (const int*)d_in[5];
    float*       out       = (float*)d_out;

    const int E = in_sizes[4] / 2;

    cudaFuncSetAttribute(quad_main, cudaFuncAttributeMaxDynamicSharedMemorySize,
                         SMEM_A_BYTES);

    detect_idx<<<1, 256>>>(eval_idx, E);
    convert_idx<<<(E + 255) / 256, 256>>>(eval_idx, E);
    prep_featT<<<dim3(N_IN / 32, 512 / 32), dim3(32, 8)>>>(features);
    quad_main<<<(E + 31) / 32, 512, SMEM_A_BYTES>>>(W1, W2, W3, eval_locs, E);
    quad_scatter<<<N_OUT, 512>>>(out, E);
}

// round 6
// speedup vs baseline: 1.7924x; 1.0750x over previous
#include <cuda_runtime.h>
#include <math.h>

typedef unsigned long long u64;

#define FMA2(d, a, b, c) \
    asm("fma.rn.f32x2 %0, %1, %2, %3;" : "=l"(d) : "l"(a), "l"(b), "l"(c))
#define PACK2(d, lo, hi) \
    asm("mov.b64 %0, {%1, %2};" : "=l"(d) : "f"(lo), "f"(hi))
#define UNPACK2(lo, hi, d) \
    asm("mov.b64 {%0, %1}, %2;" : "=f"(lo), "=f"(hi) : "l"(d))
#define LDS_V2B64(a, b, addr) \
    asm volatile("ld.shared.v2.b64 {%0, %1}, [%2];" : "=l"(a), "=l"(b) : "r"(addr))

#define N_IN   4096
#define N_OUT  1024
#define BATCH  16
#define E_MAX  81920
#define VB_STRIDE (32 * E_MAX)

__device__ float g_featT2[N_IN * 512];                 // [n][c*16+b]
__device__ float g_Vbuf[(size_t)BATCH * VB_STRIDE];
__device__ int   g_is64;
__device__ int   g_seg[E_MAX];
__device__ int   g_src[E_MAX];

// ---------------- phase -1: dtype detect + index normalize ------------------
__global__ void detect_idx(const int* __restrict__ idx32, int E) {
    __shared__ int any;
    if (threadIdx.x == 0) any = 0;
    __syncthreads();
    int n = min(E, 512);
    int local = 0;
    for (int m = threadIdx.x; m < n; m += 256)
        local |= idx32[4 * m + 1] | idx32[4 * m + 3];
    if (local) atomicOr(&any, 1);
    __syncthreads();
    if (threadIdx.x == 0) g_is64 = any ? 0 : 1;
}

__global__ void convert_idx(const int* __restrict__ idx32, int E) {
    int m = blockIdx.x * 256 + threadIdx.x;
    if (m >= E) return;
    if (g_is64) { g_seg[m] = idx32[4 * m];     g_src[m] = idx32[4 * m + 2]; }
    else        { g_seg[m] = idx32[2 * m];     g_src[m] = idx32[2 * m + 1]; }
}

// ---------------- phase 0: tiled permute feat[b][c][n] -> featT2[n][c*16+b]
__global__ void prep_featT(const float* __restrict__ feat) {
    __shared__ float tile[32][33];
    int n0  = blockIdx.x * 32;
    int cb0 = blockIdx.y * 32;
    int tx = threadIdx.x, ty = threadIdx.y;       // 32 x 8
    #pragma unroll
    for (int i = ty; i < 32; i += 8) {
        int cb = cb0 + i;
        int row = (cb & 15) * 32 + (cb >> 4);     // b*32 + c
        tile[i][tx] = feat[(size_t)row * N_IN + n0 + tx];
    }
    __syncthreads();
    #pragma unroll
    for (int i = ty; i < 32; i += 8)
        g_featT2[(size_t)(n0 + i) * 512 + cb0 + tx] = tile[tx][i];
}

// ---------------- phase A -----------------------------------------------
// 512 threads, 32 edges/block. smem (floats):
//  h1 [32][64]     @0      (2048)
//  h2t[64][36]     @2048   (2304)   transposed: h2t[k][e]
//  W2s[64][64]     @4352   (4096)
//  g  [8][16][36]  @8448   (4608)
//  filt[8][32][36] @13056  (9216)
//  locs[64]        @22272
//  goff[1024] int  @22336
#define OFF_H1   0
#define OFF_H2T  2048
#define OFF_W2S  4352
#define OFF_G    8448
#define OFF_F    13056
#define OFF_LOCS 22272
#define OFF_GOFF 22336
#define SMEM_A_FLOATS 23360
#define SMEM_A_BYTES  (SMEM_A_FLOATS * 4)

__global__ __launch_bounds__(512, 1) void quad_main(
    const float* __restrict__ W1, const float* __restrict__ W2,
    const float* __restrict__ W3, const float* __restrict__ eval_locs, int E)
{
    extern __shared__ float sm[];
    float* h1_s = sm + OFF_H1;
    float* h2t  = sm + OFF_H2T;
    float* W2s  = sm + OFF_W2S;
    float* g_s  = sm + OFF_G;
    float* f_s  = sm + OFF_F;
    float* locs = sm + OFF_LOCS;
    int*   goff = (int*)(sm + OFF_GOFF);
    const unsigned smb = (unsigned)__cvta_generic_to_shared(sm);

    const int t   = threadIdx.x;
    const int e0  = blockIdx.x * 32;
    const int net = min(32, E - e0);

    if (t < 2 * net) locs[t] = eval_locs[2 * e0 + t];

    // stage W2 into smem (coalesced, once per block)
    #pragma unroll
    for (int r = 0; r < 8; r++)
        W2s[t + 512 * r] = W2[t + 512 * r];

    // gather offsets per (e, ci): m = (e0+e)*32+ci ; channel c = m/E, row m%E
    #pragma unroll
    for (int r = 0; r < 2; r++) {
        int p = t + 512 * r;
        int e = p >> 5;
        if (e < net) {
            int m  = (e0 + e) * 32 + (p & 31);
            int c  = m / E;
            int rr = m - c * E;
            goff[p] = g_src[rr] * 512 + c * 16;
        }
    }
    __syncthreads();

    // h1[e][j] = sin(loc_e . W1[:,j])   (0 for padded edges)
    #pragma unroll
    for (int r = 0; r < 4; r++) {
        int id = t + 512 * r;
        int e = id >> 6, j = id & 63;
        float v = 0.f;
        if (e < net)
            v = __sinf(locs[2 * e] * W1[j] + locs[2 * e + 1] * W1[64 + j]);
        h1_s[id] = v;
    }
    __syncthreads();

    // ---- h2 (f32x2): thread owns (e = t>>4, cols j0..j0+3); writes h2t[j][e]
    {
        const int e  = t >> 4;
        const int j0 = (t & 15) * 4;
        u64 aA = 0ull, aB = 0ull;   // col pairs (j0,j0+1), (j0+2,j0+3)
        #pragma unroll
        for (int k4 = 0; k4 < 64; k4 += 4) {
            float4 hv = *(const float4*)&h1_s[e * 64 + k4];
            float hs[4] = {hv.x, hv.y, hv.z, hv.w};
            #pragma unroll
            for (int kk = 0; kk < 4; kk++) {
                u64 hh; PACK2(hh, hs[kk], hs[kk]);
                u64 w01, w23;
                LDS_V2B64(w01, w23, smb + (OFF_W2S + (k4 + kk) * 64 + j0) * 4);
                FMA2(aA, hh, w01, aA);
                FMA2(aB, hh, w23, aB);
            }
        }
        float s0, s1, s2, s3;
        UNPACK2(s0, s1, aA);
        UNPACK2(s2, s3, aB);
        s0 = __sinf(s0); s1 = __sinf(s1); s2 = __sinf(s2); s3 = __sinf(s3);
        if (e >= net) { s0 = s1 = s2 = s3 = 0.f; }
        h2t[(j0 + 0) * 36 + e] = s0;
        h2t[(j0 + 1) * 36 + e] = s1;
        h2t[(j0 + 2) * 36 + e] = s2;
        h2t[(j0 + 3) * 36 + e] = s3;
    }
    __syncthreads();

    // ---- filter gen (f32x2, lanes = edge pairs): thread owns cols {2t, 2t+1}
    u64 accx[16], accy[16];
    #pragma unroll
    for (int p = 0; p < 16; p++) { accx[p] = 0ull; accy[p] = 0ull; }

    const float2* w3p2 = (const float2*)W3 + t;      // row stride 512 float2
    float2 wb[4];
    #pragma unroll
    for (int j = 0; j < 4; j++) wb[j] = w3p2[j * 512];

    #pragma unroll
    for (int k4 = 0; k4 < 64; k4 += 4) {
        float2 wn[4];
        if (k4 < 60) {
            #pragma unroll
            for (int j = 0; j < 4; j++) wn[j] = w3p2[(k4 + 4 + j) * 512];
        }
        #pragma unroll
        for (int kk = 0; kk < 4; kk++) {
            const int k = k4 + kk;
            u64 wxx, wyy;
            PACK2(wxx, wb[kk].x, wb[kk].x);
            PACK2(wyy, wb[kk].y, wb[kk].y);
            const unsigned ha = smb + (OFF_H2T + k * 36) * 4;
            #pragma unroll
            for (int q = 0; q < 8; q++) {
                u64 h0, h1;                       // edges (4q,4q+1), (4q+2,4q+3)
                LDS_V2B64(h0, h1, ha + q * 16);
                FMA2(accx[2 * q],     wxx, h0, accx[2 * q]);
                FMA2(accy[2 * q],     wyy, h0, accy[2 * q]);
                FMA2(accx[2 * q + 1], wxx, h1, accx[2 * q + 1]);
                FMA2(accy[2 * q + 1], wyy, h1, accy[2 * q + 1]);
            }
        }
        #pragma unroll
        for (int j = 0; j < 4; j++) wb[j] = wn[j];
    }

    // mappings
    const int fci = t >> 4;              // filt store: col 2t -> ci
    const int fco = (t & 15) * 2;
    const int ea  = t >> 6;              // apply: edge within sub (0..7)
    const int b0  = ((t >> 3) & 7) * 2;  //        2 batches
    const int j0  = (t & 7) * 4;         //        4 consecutive co

    #pragma unroll
    for (int sub = 0; sub < 4; sub++) {
        const int es0 = sub * 8;

        // staged gather of 8 edges: g[e][b][ci]
        #pragma unroll
        for (int r = 0; r < 8; r++) {
            int i  = t + 512 * r;             // 0..4095
            int p8 = i >> 4;                  // (e,ci) 0..255
            int b  = i & 15;
            int e  = p8 >> 5, ci = p8 & 31;
            float v = (es0 + e < net) ? g_featT2[goff[(es0 + e) * 32 + ci] + b] : 0.f;
            g_s[e * 576 + b * 36 + ci] = v;
        }
        // store this sub's filters (unpack edge pairs)
        #pragma unroll
        for (int p = 0; p < 4; p++) {
            int ep = (es0 >> 1) + p;          // edge pair index
            float x0, x1, y0, y1;
            UNPACK2(x0, x1, accx[ep]);
            UNPACK2(y0, y1, accy[ep]);
            int el0 = 2 * p, el1 = 2 * p + 1; // local edge in sub
            *(float2*)&f_s[el0 * 1152 + fci * 36 + fco] = make_float2(x0, y0);
            *(float2*)&f_s[el1 * 1152 + fci * 36 + fco] = make_float2(x1, y1);
        }
        __syncthreads();

        // apply (f32x2, lanes = co pairs): 2 batches x 4 co per thread
        if (es0 + ea < net) {
            const float* gp0 = &g_s[ea * 576 + b0 * 36];
            const float* gp1 = gp0 + 36;
            const unsigned fpa = smb + (OFF_F + ea * 1152 + j0) * 4;
            u64 a001 = 0ull, a023 = 0ull, a101 = 0ull, a123 = 0ull;
            #pragma unroll
            for (int ci4 = 0; ci4 < 32; ci4 += 4) {
                float4 gv0 = *(const float4*)&gp0[ci4];
                float4 gv1 = *(const float4*)&gp1[ci4];
                float g0v[4] = {gv0.x, gv0.y, gv0.z, gv0.w};
                float g1v[4] = {gv1.x, gv1.y, gv1.z, gv1.w};
                #pragma unroll
                for (int kk = 0; kk < 4; kk++) {
                    u64 f01, f23;
                    LDS_V2B64(f01, f23, fpa + (ci4 + kk) * 36 * 4);
                    u64 d0; PACK2(d0, g0v[kk], g0v[kk]);
                    FMA2(a001, d0, f01, a001);
                    FMA2(a023, d0, f23, a023);
                    u64 d1; PACK2(d1, g1v[kk], g1v[kk]);
                    FMA2(a101, d1, f01, a101);
                    FMA2(a123, d1, f23, a123);
                }
            }
            size_t m = (size_t)(e0 + es0 + ea) * 32 + j0;
            ulonglong2 v0; v0.x = a001; v0.y = a023;
            ulonglong2 v1; v1.x = a101; v1.y = a123;
            *(ulonglong2*)&g_Vbuf[(size_t)b0       * VB_STRIDE + m] = v0;
            *(ulonglong2*)&g_Vbuf[(size_t)(b0 + 1) * VB_STRIDE + m] = v1;
        }
        __syncthreads();
    }
}

// ---------------- phase B: out[b][c][o] = sum over seg-range of Vbuf[b][c*E + r]
__global__ __launch_bounds__(512) void quad_scatter(float* __restrict__ out, int E)
{
    const int o = blockIdx.x;
    int lo = 0, hi = E;
    while (lo < hi) { int m = (lo + hi) >> 1; if (g_seg[m] <  o) lo = m + 1; else hi = m; }
    const int r0 = lo;
    hi = E;
    while (lo < hi) { int m = (lo + hi) >> 1; if (g_seg[m] <= o) lo = m + 1; else hi = m; }
    const int r1 = lo;

    const int b = threadIdx.x >> 5;
    const int l = threadIdx.x & 31;

    for (int c = 0; c < 32; c++) {
        const float* p = &g_Vbuf[(size_t)b * VB_STRIDE + (size_t)c * E];
        float s = 0.f;
        for (int r = r0 + l; r < r1; r += 32) s += p[r];
        #pragma unroll
        for (int d = 16; d; d >>= 1) s += __shfl_xor_sync(0xffffffffu, s, d);
        if (l == 0) out[b * 32768 + c * 1024 + o] = s;
    }
}

extern "C" void kernel_launch(void* const* d_in, const int* in_sizes, int n_in,
                              void* d_out, int out_size) {
    const float* features  = (const float*)d_in[0];
    const float* W1        = (const float*)d_in[1];
    const float* W2        = (const float*)d_in[2];
    const float* W3        = (const float*)d_in[3];
    const float* eval_locs = (const float*)d_in[4];
    const int*   eval_idx  = (const int*)d_in[5];
    float*       out       = (float*)d_out;

    const int E = in_sizes[4] / 2;

    cudaFuncSetAttribute(quad_main, cudaFuncAttributeMaxDynamicSharedMemorySize,
                         SMEM_A_BYTES);

    detect_idx<<<1, 256>>>(eval_idx, E);
    convert_idx<<<(E + 255) / 256, 256>>>(eval_idx, E);
    prep_featT<<<dim3(N_IN / 32, 512 / 32), dim3(32, 8)>>>(features);
    quad_main<<<(E + 31) / 32, 512, SMEM_A_BYTES>>>(W1, W2, W3, eval_locs, E);
    quad_scatter<<<N_OUT, 512>>>(out, E);
}

// round 7
// speedup vs baseline: 1.9446x; 1.0849x over previous
#include <cuda_runtime.h>
#include <math.h>

typedef unsigned long long u64;

#define FMA2(d, a, b, c) \
    asm("fma.rn.f32x2 %0, %1, %2, %3;" : "=l"(d) : "l"(a), "l"(b), "l"(c))
#define PACK2(d, lo, hi) \
    asm("mov.b64 %0, {%1, %2};" : "=l"(d) : "f"(lo), "f"(hi))
#define UNPACK2(lo, hi, d) \
    asm("mov.b64 {%0, %1}, %2;" : "=f"(lo), "=f"(hi) : "l"(d))
#define LDS_V2B64(a, b, addr) \
    asm volatile("ld.shared.v2.b64 {%0, %1}, [%2];" : "=l"(a), "=l"(b) : "r"(addr))

#define N_IN   4096
#define N_OUT  1024
#define BATCH  16
#define E_MAX  81920
#define VB_STRIDE (32 * E_MAX)

__device__ float g_featT2[N_IN * 512];                 // [n][c*16+b]
__device__ float g_Vbuf[(size_t)BATCH * VB_STRIDE];
__device__ int   g_is64;
__device__ int   g_seg[E_MAX];
__device__ int   g_src[E_MAX];

// ---------------- phase -1: dtype detect + index normalize ------------------
__global__ void detect_idx(const int* __restrict__ idx32, int E) {
    __shared__ int any;
    if (threadIdx.x == 0) any = 0;
    __syncthreads();
    int n = min(E, 512);
    int local = 0;
    for (int m = threadIdx.x; m < n; m += 256)
        local |= idx32[4 * m + 1] | idx32[4 * m + 3];
    if (local) atomicOr(&any, 1);
    __syncthreads();
    if (threadIdx.x == 0) g_is64 = any ? 0 : 1;
}

__global__ void convert_idx(const int* __restrict__ idx32, int E) {
    int m = blockIdx.x * 256 + threadIdx.x;
    if (m >= E) return;
    if (g_is64) { g_seg[m] = idx32[4 * m];     g_src[m] = idx32[4 * m + 2]; }
    else        { g_seg[m] = idx32[2 * m];     g_src[m] = idx32[2 * m + 1]; }
}

// ---------------- phase 0: tiled permute feat[b][c][n] -> featT2[n][c*16+b]
__global__ void prep_featT(const float* __restrict__ feat) {
    __shared__ float tile[32][33];
    int n0  = blockIdx.x * 32;
    int cb0 = blockIdx.y * 32;
    int tx = threadIdx.x, ty = threadIdx.y;       // 32 x 8
    #pragma unroll
    for (int i = ty; i < 32; i += 8) {
        int cb = cb0 + i;
        int row = (cb & 15) * 32 + (cb >> 4);     // b*32 + c
        tile[i][tx] = feat[(size_t)row * N_IN + n0 + tx];
    }
    __syncthreads();
    #pragma unroll
    for (int i = ty; i < 32; i += 8)
        g_featT2[(size_t)(n0 + i) * 512 + cb0 + tx] = tile[tx][i];
}

// ---------------- phase A -----------------------------------------------
// 256 threads, 16 edges/block, target 2 blocks/SM. smem (floats):
//  h1 [16][64]     @0      (1024)
//  h2t[64][20]     @1024   (1280)   transposed: h2t[k][e], pad 20
//  W2s[64][64]     @2304   (4096)
//  g  [8][16][36]  @6400   (4608)
//  filt[8][32][36] @11008  (9216)
//  locs[32]        @20224
//  goff[512] int   @20256
#define OFF_H1   0
#define OFF_H2T  1024
#define OFF_W2S  2304
#define OFF_G    6400
#define OFF_F    11008
#define OFF_LOCS 20224
#define OFF_GOFF 20256
#define SMEM_A_FLOATS 20768
#define SMEM_A_BYTES  (SMEM_A_FLOATS * 4)

__global__ __launch_bounds__(256, 2) void quad_main(
    const float* __restrict__ W1, const float* __restrict__ W2,
    const float* __restrict__ W3, const float* __restrict__ eval_locs, int E)
{
    extern __shared__ float sm[];
    float* h1_s = sm + OFF_H1;
    float* h2t  = sm + OFF_H2T;
    float* W2s  = sm + OFF_W2S;
    float* g_s  = sm + OFF_G;
    float* f_s  = sm + OFF_F;
    float* locs = sm + OFF_LOCS;
    int*   goff = (int*)(sm + OFF_GOFF);
    const unsigned smb = (unsigned)__cvta_generic_to_shared(sm);

    const int t   = threadIdx.x;
    const int e0  = blockIdx.x * 16;
    const int net = min(16, E - e0);

    if (t < 2 * net) locs[t] = eval_locs[2 * e0 + t];

    // stage W2 into smem (coalesced, once per block)
    #pragma unroll
    for (int r = 0; r < 16; r++)
        W2s[t + 256 * r] = W2[t + 256 * r];

    // gather offsets per (e, ci): m = (e0+e)*32+ci ; channel c = m/E, row m%E
    #pragma unroll
    for (int r = 0; r < 2; r++) {
        int p = t + 256 * r;              // 0..511
        int e = p >> 5;
        if (e < net) {
            int m  = (e0 + e) * 32 + (p & 31);
            int c  = m / E;
            int rr = m - c * E;
            goff[p] = g_src[rr] * 512 + c * 16;
        }
    }
    __syncthreads();

    // h1[e][j] = sin(loc_e . W1[:,j])   (0 for padded edges)
    #pragma unroll
    for (int r = 0; r < 4; r++) {
        int id = t + 256 * r;             // 0..1023
        int e = id >> 6, j = id & 63;
        float v = 0.f;
        if (e < net)
            v = __sinf(locs[2 * e] * W1[j] + locs[2 * e + 1] * W1[64 + j]);
        h1_s[id] = v;
    }
    __syncthreads();

    // ---- h2 (f32x2): thread owns (e = t>>4, cols j0..j0+3); writes h2t[j][e]
    {
        const int e  = t >> 4;
        const int j0 = (t & 15) * 4;
        u64 aA = 0ull, aB = 0ull;
        #pragma unroll
        for (int k4 = 0; k4 < 64; k4 += 4) {
            float4 hv = *(const float4*)&h1_s[e * 64 + k4];
            float hs[4] = {hv.x, hv.y, hv.z, hv.w};
            #pragma unroll
            for (int kk = 0; kk < 4; kk++) {
                u64 hh; PACK2(hh, hs[kk], hs[kk]);
                u64 w01, w23;
                LDS_V2B64(w01, w23, smb + (OFF_W2S + (k4 + kk) * 64 + j0) * 4);
                FMA2(aA, hh, w01, aA);
                FMA2(aB, hh, w23, aB);
            }
        }
        float s0, s1, s2, s3;
        UNPACK2(s0, s1, aA);
        UNPACK2(s2, s3, aB);
        s0 = __sinf(s0); s1 = __sinf(s1); s2 = __sinf(s2); s3 = __sinf(s3);
        if (e >= net) { s0 = s1 = s2 = s3 = 0.f; }
        h2t[(j0 + 0) * 20 + e] = s0;
        h2t[(j0 + 1) * 20 + e] = s1;
        h2t[(j0 + 2) * 20 + e] = s2;
        h2t[(j0 + 3) * 20 + e] = s3;
    }
    __syncthreads();

    // ---- filter gen (f32x2): thread owns 4 cols {4t..4t+3}, all 16 edges.
    // acc[c][p]: c = col 0..3, p = edge pair 0..7
    u64 acc[4][8];
    #pragma unroll
    for (int c = 0; c < 4; c++)
        #pragma unroll
        for (int p = 0; p < 8; p++) acc[c][p] = 0ull;

    const float4* w3p4 = (const float4*)W3 + t;     // row stride 256 float4
    float4 wcur = w3p4[0];

    #pragma unroll 8
    for (int k = 0; k < 64; k++) {
        float4 wnext = (k < 63) ? w3p4[(k + 1) * 256] : wcur;
        u64 wa, wb, wc, wd;
        PACK2(wa, wcur.x, wcur.x);
        PACK2(wb, wcur.y, wcur.y);
        PACK2(wc, wcur.z, wcur.z);
        PACK2(wd, wcur.w, wcur.w);
        const unsigned ha = smb + (OFF_H2T + k * 20) * 4;
        u64 hp[8];
        LDS_V2B64(hp[0], hp[1], ha);
        LDS_V2B64(hp[2], hp[3], ha + 16);
        LDS_V2B64(hp[4], hp[5], ha + 32);
        LDS_V2B64(hp[6], hp[7], ha + 48);
        #pragma unroll
        for (int p = 0; p < 8; p++) {
            FMA2(acc[0][p], wa, hp[p], acc[0][p]);
            FMA2(acc[1][p], wb, hp[p], acc[1][p]);
            FMA2(acc[2][p], wc, hp[p], acc[2][p]);
            FMA2(acc[3][p], wd, hp[p], acc[3][p]);
        }
        wcur = wnext;
    }

    // mappings
    const int fci = t >> 3;              // filt store: col 4t -> ci
    const int fco = (t & 7) * 4;
    const int ea  = t >> 5;              // apply: edge within sub (0..7)
    const int b0  = ((t >> 2) & 7) * 2;  //        2 batches
    const int j0  = (t & 3) * 8;         //        8 consecutive co

    #pragma unroll
    for (int sub = 0; sub < 2; sub++) {
        const int es0 = sub * 8;

        // staged gather of 8 edges: g[e][b][ci]
        #pragma unroll
        for (int r = 0; r < 16; r++) {
            int i  = t + 256 * r;             // 0..4095
            int p8 = i >> 4;                  // (e,ci) 0..255
            int b  = i & 15;
            int e  = p8 >> 5, ci = p8 & 31;
            float v = (es0 + e < net) ? g_featT2[goff[(es0 + e) * 32 + ci] + b] : 0.f;
            g_s[e * 576 + b * 36 + ci] = v;
        }
        // store this sub's filters: edge pairs 4*sub..4*sub+3
        #pragma unroll
        for (int p = 0; p < 4; p++) {
            int pp = sub * 4 + p;
            float x0, x1, y0, y1, z0, z1, w0, w1;
            UNPACK2(x0, x1, acc[0][pp]);
            UNPACK2(y0, y1, acc[1][pp]);
            UNPACK2(z0, z1, acc[2][pp]);
            UNPACK2(w0, w1, acc[3][pp]);
            *(float4*)&f_s[(2 * p)     * 1152 + fci * 36 + fco] = make_float4(x0, y0, z0, w0);
            *(float4*)&f_s[(2 * p + 1) * 1152 + fci * 36 + fco] = make_float4(x1, y1, z1, w1);
        }
        __syncthreads();

        // apply (f32x2): 2 batches x 8 co per thread, one edge
        if (es0 + ea < net) {
            const float* gp0 = &g_s[ea * 576 + b0 * 36];
            const float* gp1 = gp0 + 36;
            const unsigned fpa = smb + (OFF_F + ea * 1152 + j0) * 4;
            u64 a0[4] = {0ull, 0ull, 0ull, 0ull};
            u64 a1[4] = {0ull, 0ull, 0ull, 0ull};
            #pragma unroll
            for (int ci4 = 0; ci4 < 32; ci4 += 4) {
                float4 gv0 = *(const float4*)&gp0[ci4];
                float4 gv1 = *(const float4*)&gp1[ci4];
                float g0v[4] = {gv0.x, gv0.y, gv0.z, gv0.w};
                float g1v[4] = {gv1.x, gv1.y, gv1.z, gv1.w};
                #pragma unroll
                for (int kk = 0; kk < 4; kk++) {
                    u64 f01, f23, f45, f67;
                    LDS_V2B64(f01, f23, fpa + (ci4 + kk) * 144);
                    LDS_V2B64(f45, f67, fpa + (ci4 + kk) * 144 + 16);
                    u64 d0; PACK2(d0, g0v[kk], g0v[kk]);
                    FMA2(a0[0], d0, f01, a0[0]);
                    FMA2(a0[1], d0, f23, a0[1]);
                    FMA2(a0[2], d0, f45, a0[2]);
                    FMA2(a0[3], d0, f67, a0[3]);
                    u64 d1; PACK2(d1, g1v[kk], g1v[kk]);
                    FMA2(a1[0], d1, f01, a1[0]);
                    FMA2(a1[1], d1, f23, a1[1]);
                    FMA2(a1[2], d1, f45, a1[2]);
                    FMA2(a1[3], d1, f67, a1[3]);
                }
            }
            size_t m = (size_t)(e0 + es0 + ea) * 32 + j0;
            float* vb0 = &g_Vbuf[(size_t)b0 * VB_STRIDE + m];
            float* vb1 = vb0 + VB_STRIDE;
            ulonglong2 s0a; s0a.x = a0[0]; s0a.y = a0[1];
            ulonglong2 s0b; s0b.x = a0[2]; s0b.y = a0[3];
            ulonglong2 s1a; s1a.x = a1[0]; s1a.y = a1[1];
            ulonglong2 s1b; s1b.x = a1[2]; s1b.y = a1[3];
            *(ulonglong2*)vb0       = s0a;
            *(ulonglong2*)(vb0 + 4) = s0b;
            *(ulonglong2*)vb1       = s1a;
            *(ulonglong2*)(vb1 + 4) = s1b;
        }
        __syncthreads();
    }
}

// ---------------- phase B: out[b][c][o] = sum over seg-range of Vbuf[b][c*E + r]
__global__ __launch_bounds__(512) void quad_scatter(float* __restrict__ out, int E)
{
    const int o = blockIdx.x;
    int lo = 0, hi = E;
    while (lo < hi) { int m = (lo + hi) >> 1; if (g_seg[m] <  o) lo = m + 1; else hi = m; }
    const int r0 = lo;
    hi = E;
    while (lo < hi) { int m = (lo + hi) >> 1; if (g_seg[m] <= o) lo = m + 1; else hi = m; }
    const int r1 = lo;

    const int b = threadIdx.x >> 5;
    const int l = threadIdx.x & 31;

    for (int c = 0; c < 32; c++) {
        const float* p = &g_Vbuf[(size_t)b * VB_STRIDE + (size_t)c * E];
        float s = 0.f;
        for (int r = r0 + l; r < r1; r += 32) s += p[r];
        #pragma unroll
        for (int d = 16; d; d >>= 1) s += __shfl_xor_sync(0xffffffffu, s, d);
        if (l == 0) out[b * 32768 + c * 1024 + o] = s;
    }
}

extern "C" void kernel_launch(void* const* d_in, const int* in_sizes, int n_in,
                              void* d_out, int out_size) {
    const float* features  = (const float*)d_in[0];
    const float* W1        = (const float*)d_in[1];
    const float* W2        = (const float*)d_in[2];
    const float* W3        = (const float*)d_in[3];
    const float* eval_locs = (const float*)d_in[4];
    const int*   eval_idx  = (const int*)d_in[5];
    float*       out       = (float*)d_out;

    const int E = in_sizes[4] / 2;

    cudaFuncSetAttribute(quad_main, cudaFuncAttributeMaxDynamicSharedMemorySize,
                         SMEM_A_BYTES);

    detect_idx<<<1, 256>>>(eval_idx, E);
    convert_idx<<<(E + 255) / 256, 256>>>(eval_idx, E);
    prep_featT<<<dim3(N_IN / 32, 512 / 32), dim3(32, 8)>>>(features);
    quad_main<<<(E + 15) / 16, 256, SMEM_A_BYTES>>>(W1, W2, W3, eval_locs, E);
    quad_scatter<<<N_OUT, 512>>>(out, E);
}